// round 9
// baseline (speedup 1.0000x reference)
#include <cuda_runtime.h>

#define TH 16
#define TW 64
#define NT 256
#define HIMG 512
#define WIMG 512
#define SAW 68   // padded row stride for s_a
#define SCW 36   // padded row stride for s_c (half-res chroma)

__constant__ float c_D[64];   // DCT matrix, row-major

__device__ __forceinline__ float dot8(const float4 a0, const float4 a1,
                                      const float4 b0, const float4 b1) {
    return fmaf(a1.w, b1.w, fmaf(a1.z, b1.z, fmaf(a1.y, b1.y,
           fmaf(a1.x, b1.x, fmaf(a0.w, b0.w, fmaf(a0.z, b0.z,
           fmaf(a0.y, b0.y, a0.x * b0.x)))))));
}

__global__ __launch_bounds__(NT, 5) void jpeg_kernel(
    const float* __restrict__ in, const float* __restrict__ quant,
    const float* __restrict__ dct, float* __restrict__ out)
{
    __shared__ __align__(16) float s_a[3][TH][SAW];   // X / T1^T / W / Z
    __shared__ __align__(16) float s_c[2][TH/2][SCW]; // half-res chroma
    __shared__ __align__(16) float s_qt[3][8][8];     // q transposed: qt[c][i][l]=q[l][i]
    __shared__ __align__(16) float s_rqt[3][8][8];    // 1/q transposed

    const int tid = threadIdx.x;
    const int b   = blockIdx.z;
    const int ty0 = blockIdx.y * TH;
    const int tx0 = blockIdx.x * TW;

    // ---- tables (transposed quant) ----
    if (tid < 192) {
        int i = tid;
        float qv = rintf(quant[i] * 255.0f);
        float q1 = rintf((qv * 50.0f + 50.0f) / 100.0f);
        float q  = fminf(fmaxf(q1, 1.0f), 255.0f);
        int ci = i >> 6, ri = (i >> 3) & 7, li = i & 7;
        s_qt[ci][li][ri]  = q;
        s_rqt[ci][li][ri] = 1.0f / q;
    }

    const size_t plane = (size_t)HIMG * WIMG;
    const float* base  = in  + (size_t)b * 3 * plane;
    float*       obase = out + (size_t)b * 3 * plane;

    // ---- phase 1: 4x1 strips (LDG.128); chroma 2x2 mean via in-warp shuffle ----
    {
        const int sy = tid >> 4;
        const int sx = tid & 15;
        const int px = sx * 4;
        const size_t idx = (size_t)(ty0 + sy) * WIMG + (tx0 + px);

        const float4 r4 = *(const float4*)&base[idx];
        const float4 g4 = *(const float4*)&base[plane + idx];
        const float4 b4 = *(const float4*)&base[2*plane + idx];

        float R[4] = {255.0f*r4.x, 255.0f*r4.y, 255.0f*r4.z, 255.0f*r4.w};
        float G[4] = {255.0f*g4.x, 255.0f*g4.y, 255.0f*g4.z, 255.0f*g4.w};
        float B[4] = {255.0f*b4.x, 255.0f*b4.y, 255.0f*b4.z, 255.0f*b4.w};

        #define YV(R_,G_,B_)  fmaf(0.114f,(B_), fmaf(0.587f,(G_), 0.299f*(R_)))
        #define CBV(R_,G_,B_) (fmaf(0.5f,(B_),  fmaf(-0.331264108f,(G_), -0.168735892f*(R_))) + 128.0f)
        #define CRV(R_,G_,B_) (fmaf(-0.081312411f,(B_), fmaf(-0.418687589f,(G_), 0.5f*(R_))) + 128.0f)
        #define CL(v) fminf(fmaxf((v), 0.0f), 255.0f)

        float Y[4], CB[4], CR[4];
        #pragma unroll
        for (int e = 0; e < 4; e++) {
            Y[e]  = CL(YV(R[e], G[e], B[e])) - 128.0f;
            CB[e] = CL(CBV(R[e], G[e], B[e]));
            CR[e] = CL(CRV(R[e], G[e], B[e]));
        }
        *(float4*)&s_a[0][sy][px] = make_float4(Y[0], Y[1], Y[2], Y[3]);

        float pcb0 = __shfl_xor_sync(0xffffffffu, CB[0], 16);
        float pcb1 = __shfl_xor_sync(0xffffffffu, CB[1], 16);
        float pcb2 = __shfl_xor_sync(0xffffffffu, CB[2], 16);
        float pcb3 = __shfl_xor_sync(0xffffffffu, CB[3], 16);
        float pcr0 = __shfl_xor_sync(0xffffffffu, CR[0], 16);
        float pcr1 = __shfl_xor_sync(0xffffffffu, CR[1], 16);
        float pcr2 = __shfl_xor_sync(0xffffffffu, CR[2], 16);
        float pcr3 = __shfl_xor_sync(0xffffffffu, CR[3], 16);
        if ((sy & 1) == 0) {
            float cbm0 = 0.25f * (((CB[0] + CB[1]) + pcb0) + pcb1) - 128.0f;
            float cbm1 = 0.25f * (((CB[2] + CB[3]) + pcb2) + pcb3) - 128.0f;
            float crm0 = 0.25f * (((CR[0] + CR[1]) + pcr0) + pcr1) - 128.0f;
            float crm1 = 0.25f * (((CR[2] + CR[3]) + pcr2) + pcr3) - 128.0f;
            *(float2*)&s_c[0][sy >> 1][sx*2] = make_float2(cbm0, cbm1);
            *(float2*)&s_c[1][sy >> 1][sx*2] = make_float2(crm0, crm1);
        }
    }
    __syncthreads();

    // ---- assignment: 48 units * 4 threads; thread owns rows {2r, 2r+1} ----
    const bool act = tid < 192;
    const int unit = tid >> 2;    // 0..47
    const int r    = tid & 3;
    int c, by, bx;
    if (unit < 16) { c = 0; by = unit >> 3; bx = unit & 7; }
    else { int t = unit - 16; c = 1 + (t >> 4); int rem = t & 15; by = rem >> 3; bx = rem & 7; }
    const int ra = 2 * r, rb = 2 * r + 1;
    float* pW = &s_a[c][by*8][bx*8];

    if (act) {
        // ==== stage A: T1 = X*D^T (luma) / T1c = Xh*E^T (chroma); write transposed ====
        float Aa[8], Ab[8];
        if (c == 0) {
            const float4 xa0 = *(const float4*)(pW + ra*SAW);
            const float4 xa1 = *(const float4*)(pW + ra*SAW + 4);
            const float4 xb0 = *(const float4*)(pW + rb*SAW);
            const float4 xb1 = *(const float4*)(pW + rb*SAW + 4);
            #pragma unroll
            for (int l = 0; l < 8; l++) {
                const float4 d0 = *(const float4*)&c_D[l*8];
                const float4 d1 = *(const float4*)&c_D[l*8 + 4];
                Aa[l] = dot8(xa0, xa1, d0, d1);
                Ab[l] = dot8(xb0, xb1, d0, d1);
            }
        } else {
            const float* pC = &s_c[c-1][by*4][bx*4];
            const float4 xh = *(const float4*)(pC + r*SCW);
            #pragma unroll
            for (int l = 0; l < 8; l++) {
                const float4 d0 = *(const float4*)&c_D[l*8];
                const float4 d1 = *(const float4*)&c_D[l*8 + 4];
                float e0 = d0.x + d0.y, e1 = d0.z + d0.w;
                float e2 = d1.x + d1.y, e3 = d1.z + d1.w;
                Aa[l] = fmaf(xh.w, e3, fmaf(xh.z, e2, fmaf(xh.y, e1, xh.x * e0)));
            }
        }
        __syncwarp();   // all X/Xh reads done -> safe to overwrite block
        if (c == 0) {
            #pragma unroll
            for (int j = 0; j < 8; j++)
                *(float2*)(pW + j*SAW + ra) = make_float2(Aa[j], Ab[j]);  // cols 2r,2r+1
        } else {
            #pragma unroll
            for (int j = 0; j < 8; j++)
                pW[j*SAW + r] = Aa[j];                                     // col r (T1c^T is 8x4)
        }
        __syncwarp();

        // ==== stage B+C fused: Y2^T = T1^T*D^T, quant/dequant, G = Y2'^T*D ====
        float ta[8], tb[8];
        if (c == 0) {
            *(float4*)&ta[0] = *(const float4*)(pW + ra*SAW);
            *(float4*)&ta[4] = *(const float4*)(pW + ra*SAW + 4);
            *(float4*)&tb[0] = *(const float4*)(pW + rb*SAW);
            *(float4*)&tb[4] = *(const float4*)(pW + rb*SAW + 4);
        } else {
            *(float4*)&ta[0] = *(const float4*)(pW + ra*SAW);   // 4-wide rows
            *(float4*)&tb[0] = *(const float4*)(pW + rb*SAW);
        }

        float Ga[8], Gb[8];
        {
            // row ra
            float Ya[8];
            if (c == 0) {
                const float4 a0 = *(const float4*)&ta[0];
                const float4 a1 = *(const float4*)&ta[4];
                #pragma unroll
                for (int l = 0; l < 8; l++) {
                    const float4 d0 = *(const float4*)&c_D[l*8];
                    const float4 d1 = *(const float4*)&c_D[l*8 + 4];
                    Ya[l] = dot8(a0, a1, d0, d1);
                }
            } else {
                const float4 a0 = *(const float4*)&ta[0];
                #pragma unroll
                for (int l = 0; l < 8; l++) {
                    const float4 d0 = *(const float4*)&c_D[l*8];
                    const float4 d1 = *(const float4*)&c_D[l*8 + 4];
                    float e0 = d0.x + d0.y, e1 = d0.z + d0.w;
                    float e2 = d1.x + d1.y, e3 = d1.z + d1.w;
                    Ya[l] = fmaf(a0.w, e3, fmaf(a0.z, e2, fmaf(a0.y, e1, a0.x * e0)));
                }
            }
            {
                const float4 q0  = *(const float4*)&s_qt[c][ra][0];
                const float4 q1  = *(const float4*)&s_qt[c][ra][4];
                const float4 rq0 = *(const float4*)&s_rqt[c][ra][0];
                const float4 rq1 = *(const float4*)&s_rqt[c][ra][4];
                Ya[0] = rintf(rintf(Ya[0]*rq0.x)*q0.x);  Ya[1] = rintf(rintf(Ya[1]*rq0.y)*q0.y);
                Ya[2] = rintf(rintf(Ya[2]*rq0.z)*q0.z);  Ya[3] = rintf(rintf(Ya[3]*rq0.w)*q0.w);
                Ya[4] = rintf(rintf(Ya[4]*rq1.x)*q1.x);  Ya[5] = rintf(rintf(Ya[5]*rq1.y)*q1.y);
                Ya[6] = rintf(rintf(Ya[6]*rq1.z)*q1.z);  Ya[7] = rintf(rintf(Ya[7]*rq1.w)*q1.w);
            }
            #pragma unroll
            for (int l = 0; l < 8; l++) Ga[l] = 0.0f;
            #pragma unroll
            for (int k = 0; k < 8; k++) {
                const float4 d0 = *(const float4*)&c_D[k*8];
                const float4 d1 = *(const float4*)&c_D[k*8 + 4];
                const float t = Ya[k];
                Ga[0] = fmaf(t, d0.x, Ga[0]);  Ga[1] = fmaf(t, d0.y, Ga[1]);
                Ga[2] = fmaf(t, d0.z, Ga[2]);  Ga[3] = fmaf(t, d0.w, Ga[3]);
                Ga[4] = fmaf(t, d1.x, Ga[4]);  Ga[5] = fmaf(t, d1.y, Ga[5]);
                Ga[6] = fmaf(t, d1.z, Ga[6]);  Ga[7] = fmaf(t, d1.w, Ga[7]);
            }
            // row rb
            float Yb[8];
            if (c == 0) {
                const float4 a0 = *(const float4*)&tb[0];
                const float4 a1 = *(const float4*)&tb[4];
                #pragma unroll
                for (int l = 0; l < 8; l++) {
                    const float4 d0 = *(const float4*)&c_D[l*8];
                    const float4 d1 = *(const float4*)&c_D[l*8 + 4];
                    Yb[l] = dot8(a0, a1, d0, d1);
                }
            } else {
                const float4 a0 = *(const float4*)&tb[0];
                #pragma unroll
                for (int l = 0; l < 8; l++) {
                    const float4 d0 = *(const float4*)&c_D[l*8];
                    const float4 d1 = *(const float4*)&c_D[l*8 + 4];
                    float e0 = d0.x + d0.y, e1 = d0.z + d0.w;
                    float e2 = d1.x + d1.y, e3 = d1.z + d1.w;
                    Yb[l] = fmaf(a0.w, e3, fmaf(a0.z, e2, fmaf(a0.y, e1, a0.x * e0)));
                }
            }
            {
                const float4 q0  = *(const float4*)&s_qt[c][rb][0];
                const float4 q1  = *(const float4*)&s_qt[c][rb][4];
                const float4 rq0 = *(const float4*)&s_rqt[c][rb][0];
                const float4 rq1 = *(const float4*)&s_rqt[c][rb][4];
                Yb[0] = rintf(rintf(Yb[0]*rq0.x)*q0.x);  Yb[1] = rintf(rintf(Yb[1]*rq0.y)*q0.y);
                Yb[2] = rintf(rintf(Yb[2]*rq0.z)*q0.z);  Yb[3] = rintf(rintf(Yb[3]*rq0.w)*q0.w);
                Yb[4] = rintf(rintf(Yb[4]*rq1.x)*q1.x);  Yb[5] = rintf(rintf(Yb[5]*rq1.y)*q1.y);
                Yb[6] = rintf(rintf(Yb[6]*rq1.z)*q1.z);  Yb[7] = rintf(rintf(Yb[7]*rq1.w)*q1.w);
            }
            #pragma unroll
            for (int l = 0; l < 8; l++) Gb[l] = 0.0f;
            #pragma unroll
            for (int k = 0; k < 8; k++) {
                const float4 d0 = *(const float4*)&c_D[k*8];
                const float4 d1 = *(const float4*)&c_D[k*8 + 4];
                const float t = Yb[k];
                Gb[0] = fmaf(t, d0.x, Gb[0]);  Gb[1] = fmaf(t, d0.y, Gb[1]);
                Gb[2] = fmaf(t, d0.z, Gb[2]);  Gb[3] = fmaf(t, d0.w, Gb[3]);
                Gb[4] = fmaf(t, d1.x, Gb[4]);  Gb[5] = fmaf(t, d1.y, Gb[5]);
                Gb[6] = fmaf(t, d1.z, Gb[6]);  Gb[7] = fmaf(t, d1.w, Gb[7]);
            }
        }
        __syncwarp();   // all T1^T reads done -> safe to overwrite
        #pragma unroll
        for (int j = 0; j < 8; j++)
            *(float2*)(pW + j*SAW + ra) = make_float2(Ga[j], Gb[j]);  // W = D^T*Y2'
        __syncwarp();

        // ==== stage D: Z = W*D (row-local), +off, write normal ====
        float wa[8], wb[8];
        *(float4*)&wa[0] = *(const float4*)(pW + ra*SAW);
        *(float4*)&wa[4] = *(const float4*)(pW + ra*SAW + 4);
        *(float4*)&wb[0] = *(const float4*)(pW + rb*SAW);
        *(float4*)&wb[4] = *(const float4*)(pW + rb*SAW + 4);
        float Za[8], Zb[8];
        #pragma unroll
        for (int l = 0; l < 8; l++) { Za[l] = 0.0f; Zb[l] = 0.0f; }
        #pragma unroll
        for (int k = 0; k < 8; k++) {
            const float4 d0 = *(const float4*)&c_D[k*8];
            const float4 d1 = *(const float4*)&c_D[k*8 + 4];
            const float t0 = wa[k], t1 = wb[k];
            Za[0] = fmaf(t0, d0.x, Za[0]);  Zb[0] = fmaf(t1, d0.x, Zb[0]);
            Za[1] = fmaf(t0, d0.y, Za[1]);  Zb[1] = fmaf(t1, d0.y, Zb[1]);
            Za[2] = fmaf(t0, d0.z, Za[2]);  Zb[2] = fmaf(t1, d0.z, Zb[2]);
            Za[3] = fmaf(t0, d0.w, Za[3]);  Zb[3] = fmaf(t1, d0.w, Zb[3]);
            Za[4] = fmaf(t0, d1.x, Za[4]);  Zb[4] = fmaf(t1, d1.x, Zb[4]);
            Za[5] = fmaf(t0, d1.y, Za[5]);  Zb[5] = fmaf(t1, d1.y, Zb[5]);
            Za[6] = fmaf(t0, d1.z, Za[6]);  Zb[6] = fmaf(t1, d1.z, Zb[6]);
            Za[7] = fmaf(t0, d1.w, Za[7]);  Zb[7] = fmaf(t1, d1.w, Zb[7]);
        }
        const float off = (c == 0) ? 128.0f : 0.0f;
        #pragma unroll
        for (int l = 0; l < 8; l++) { Za[l] += off; Zb[l] += off; }
        // each thread reads/writes only its own rows here: no barrier needed
        *(float4*)(pW + ra*SAW)     = make_float4(Za[0], Za[1], Za[2], Za[3]);
        *(float4*)(pW + ra*SAW + 4) = make_float4(Za[4], Za[5], Za[6], Za[7]);
        *(float4*)(pW + rb*SAW)     = make_float4(Zb[0], Zb[1], Zb[2], Zb[3]);
        *(float4*)(pW + rb*SAW + 4) = make_float4(Zb[4], Zb[5], Zb[6], Zb[7]);
    }
    __syncthreads();

    // ---- phase 5: YCbCr -> RGB, clip, round, store ----
    {
        const int py  = tid >> 4;
        const int px4 = (tid & 15) * 4;
        const float4 yv  = *(const float4*)&s_a[0][py][px4];
        const float4 cbv = *(const float4*)&s_a[1][py][px4];
        const float4 crv = *(const float4*)&s_a[2][py][px4];

        #define FIN(v) (rintf(fminf(fmaxf((v), 0.0f), 255.0f)) * (1.0f/255.0f))
        float4 R, G, Bv;
        R.x = FIN(fmaf(1.402f, crv.x, yv.x));  R.y = FIN(fmaf(1.402f, crv.y, yv.y));
        R.z = FIN(fmaf(1.402f, crv.z, yv.z));  R.w = FIN(fmaf(1.402f, crv.w, yv.w));
        G.x = FIN(fmaf(-0.714136286f, crv.x, fmaf(-0.344136286f, cbv.x, yv.x)));
        G.y = FIN(fmaf(-0.714136286f, crv.y, fmaf(-0.344136286f, cbv.y, yv.y)));
        G.z = FIN(fmaf(-0.714136286f, crv.z, fmaf(-0.344136286f, cbv.z, yv.z)));
        G.w = FIN(fmaf(-0.714136286f, crv.w, fmaf(-0.344136286f, cbv.w, yv.w)));
        Bv.x = FIN(fmaf(1.772f, cbv.x, yv.x)); Bv.y = FIN(fmaf(1.772f, cbv.y, yv.y));
        Bv.z = FIN(fmaf(1.772f, cbv.z, yv.z)); Bv.w = FIN(fmaf(1.772f, cbv.w, yv.w));

        const size_t idx = (size_t)(ty0 + py) * WIMG + (tx0 + px4);
        *(float4*)&obase[idx]           = R;
        *(float4*)&obase[plane + idx]   = G;
        *(float4*)&obase[2*plane + idx] = Bv;
    }
}

extern "C" void kernel_launch(void* const* d_in, const int* in_sizes, int n_in,
                              void* d_out, int out_size)
{
    const float* x = nullptr;
    const float* q = nullptr;
    const float* d = nullptr;
    int nimg = 0;
    for (int i = 0; i < n_in; i++) {
        if (in_sizes[i] == 192)      q = (const float*)d_in[i];
        else if (in_sizes[i] == 64)  d = (const float*)d_in[i];
        else { x = (const float*)d_in[i]; nimg = in_sizes[i] / (3 * HIMG * WIMG); }
    }
    cudaMemcpyToSymbolAsync(c_D, d, 64 * sizeof(float), 0,
                            cudaMemcpyDeviceToDevice, 0);
    dim3 grid(WIMG / TW, HIMG / TH, nimg);
    jpeg_kernel<<<grid, NT>>>(x, q, d, (float*)d_out);
}

// round 10
// speedup vs baseline: 1.5201x; 1.5201x over previous
#include <cuda_runtime.h>

#define TH 16
#define TW 64
#define NT 256
#define HIMG 512
#define WIMG 512
#define SAW 68   // padded row stride for s_a
#define SCW 36   // padded row stride for s_c (half-res chroma)

__constant__ float c_D[64];   // DCT matrix, row-major

__device__ __forceinline__ float dot8(const float4 a0, const float4 a1,
                                      const float4 b0, const float4 b1) {
    return fmaf(a1.w, b1.w, fmaf(a1.z, b1.z, fmaf(a1.y, b1.y,
           fmaf(a1.x, b1.x, fmaf(a0.w, b0.w, fmaf(a0.z, b0.z,
           fmaf(a0.y, b0.y, a0.x * b0.x)))))));
}

__global__ __launch_bounds__(NT, 4) void jpeg_kernel(
    const float* __restrict__ in, const float* __restrict__ quant,
    const float* __restrict__ dct, float* __restrict__ out)
{
    __shared__ __align__(16) float s_a[3][TH][SAW];   // X / T1^T / W / Z
    __shared__ __align__(16) float s_c[2][TH/2][SCW]; // half-res chroma
    __shared__ __align__(16) float s_qt[3][8][8];     // q transposed
    __shared__ __align__(16) float s_rqt[3][8][8];    // 1/q transposed

    const int tid = threadIdx.x;
    const int b   = blockIdx.z;
    const int ty0 = blockIdx.y * TH;
    const int tx0 = blockIdx.x * TW;

    // ---- tables (transposed quant) ----
    if (tid < 192) {
        int i = tid;
        float qv = rintf(quant[i] * 255.0f);
        float q1 = rintf((qv * 50.0f + 50.0f) / 100.0f);
        float q  = fminf(fmaxf(q1, 1.0f), 255.0f);
        int ci = i >> 6, ri = (i >> 3) & 7, li = i & 7;
        s_qt[ci][li][ri]  = q;
        s_rqt[ci][li][ri] = 1.0f / q;
    }

    const size_t plane = (size_t)HIMG * WIMG;
    const float* base  = in  + (size_t)b * 3 * plane;
    float*       obase = out + (size_t)b * 3 * plane;

    // ---- phase 1: 4x1 strips (LDG.128); chroma 2x2 mean via in-warp shuffle ----
    {
        const int sy = tid >> 4;
        const int sx = tid & 15;
        const int px = sx * 4;
        const size_t idx = (size_t)(ty0 + sy) * WIMG + (tx0 + px);

        const float4 r4 = *(const float4*)&base[idx];
        const float4 g4 = *(const float4*)&base[plane + idx];
        const float4 b4 = *(const float4*)&base[2*plane + idx];

        float R[4] = {255.0f*r4.x, 255.0f*r4.y, 255.0f*r4.z, 255.0f*r4.w};
        float G[4] = {255.0f*g4.x, 255.0f*g4.y, 255.0f*g4.z, 255.0f*g4.w};
        float B[4] = {255.0f*b4.x, 255.0f*b4.y, 255.0f*b4.z, 255.0f*b4.w};

        #define YV(R_,G_,B_)  fmaf(0.114f,(B_), fmaf(0.587f,(G_), 0.299f*(R_)))
        #define CBV(R_,G_,B_) (fmaf(0.5f,(B_),  fmaf(-0.331264108f,(G_), -0.168735892f*(R_))) + 128.0f)
        #define CRV(R_,G_,B_) (fmaf(-0.081312411f,(B_), fmaf(-0.418687589f,(G_), 0.5f*(R_))) + 128.0f)
        #define CL(v) fminf(fmaxf((v), 0.0f), 255.0f)

        float Y[4], CB[4], CR[4];
        #pragma unroll
        for (int e = 0; e < 4; e++) {
            Y[e]  = CL(YV(R[e], G[e], B[e])) - 128.0f;
            CB[e] = CL(CBV(R[e], G[e], B[e]));
            CR[e] = CL(CRV(R[e], G[e], B[e]));
        }
        *(float4*)&s_a[0][sy][px] = make_float4(Y[0], Y[1], Y[2], Y[3]);

        float pcb0 = __shfl_xor_sync(0xffffffffu, CB[0], 16);
        float pcb1 = __shfl_xor_sync(0xffffffffu, CB[1], 16);
        float pcb2 = __shfl_xor_sync(0xffffffffu, CB[2], 16);
        float pcb3 = __shfl_xor_sync(0xffffffffu, CB[3], 16);
        float pcr0 = __shfl_xor_sync(0xffffffffu, CR[0], 16);
        float pcr1 = __shfl_xor_sync(0xffffffffu, CR[1], 16);
        float pcr2 = __shfl_xor_sync(0xffffffffu, CR[2], 16);
        float pcr3 = __shfl_xor_sync(0xffffffffu, CR[3], 16);
        if ((sy & 1) == 0) {
            float cbm0 = 0.25f * (((CB[0] + CB[1]) + pcb0) + pcb1) - 128.0f;
            float cbm1 = 0.25f * (((CB[2] + CB[3]) + pcb2) + pcb3) - 128.0f;
            float crm0 = 0.25f * (((CR[0] + CR[1]) + pcr0) + pcr1) - 128.0f;
            float crm1 = 0.25f * (((CR[2] + CR[3]) + pcr2) + pcr3) - 128.0f;
            *(float2*)&s_c[0][sy >> 1][sx*2] = make_float2(cbm0, cbm1);
            *(float2*)&s_c[1][sy >> 1][sx*2] = make_float2(crm0, crm1);
        }
    }
    __syncthreads();

    // ---- assignment: 48 units * 4 threads; thread owns rows {2r, 2r+1} ----
    const bool act = tid < 192;
    const int unit = tid >> 2;
    const int r    = tid & 3;
    int c, by, bx;
    if (unit < 16) { c = 0; by = unit >> 3; bx = unit & 7; }
    else { int t = unit - 16; c = 1 + (t >> 4); int rem = t & 15; by = rem >> 3; bx = rem & 7; }
    const int ra = 2 * r, rb = 2 * r + 1;
    float* pW = &s_a[c][by*8][bx*8];

    if (act) {
        // ==== stage A: T1 = X*D^T (luma) / T1c = Xh*E^T (chroma); write transposed ====
        {
            float Aa[8], Ab[8];
            if (c == 0) {
                const float4 xa0 = *(const float4*)(pW + ra*SAW);
                const float4 xa1 = *(const float4*)(pW + ra*SAW + 4);
                const float4 xb0 = *(const float4*)(pW + rb*SAW);
                const float4 xb1 = *(const float4*)(pW + rb*SAW + 4);
                #pragma unroll
                for (int l = 0; l < 8; l++) {
                    const float4 d0 = *(const float4*)&c_D[l*8];
                    const float4 d1 = *(const float4*)&c_D[l*8 + 4];
                    Aa[l] = dot8(xa0, xa1, d0, d1);
                    Ab[l] = dot8(xb0, xb1, d0, d1);
                }
                __syncwarp();
                #pragma unroll
                for (int j = 0; j < 8; j++)
                    *(float2*)(pW + j*SAW + ra) = make_float2(Aa[j], Ab[j]);
            } else {
                const float* pC = &s_c[c-1][by*4][bx*4];
                const float4 xh = *(const float4*)(pC + r*SCW);
                #pragma unroll
                for (int l = 0; l < 8; l++) {
                    const float4 d0 = *(const float4*)&c_D[l*8];
                    const float4 d1 = *(const float4*)&c_D[l*8 + 4];
                    float e0 = d0.x + d0.y, e1 = d0.z + d0.w;
                    float e2 = d1.x + d1.y, e3 = d1.z + d1.w;
                    Aa[l] = fmaf(xh.w, e3, fmaf(xh.z, e2, fmaf(xh.y, e1, xh.x * e0)));
                }
                __syncwarp();
                #pragma unroll
                for (int j = 0; j < 8; j++)
                    pW[j*SAW + r] = Aa[j];
            }
        }
        __syncwarp();

        // ==== stage B: Y2^T rows = T1^T*D^T (or *E^T), quant/dequant ====
        float Ya[8], Yb[8];
        if (c == 0) {
            const float4 a0 = *(const float4*)(pW + ra*SAW);
            const float4 a1 = *(const float4*)(pW + ra*SAW + 4);
            const float4 b0 = *(const float4*)(pW + rb*SAW);
            const float4 b1 = *(const float4*)(pW + rb*SAW + 4);
            #pragma unroll
            for (int l = 0; l < 8; l++) {
                const float4 d0 = *(const float4*)&c_D[l*8];
                const float4 d1 = *(const float4*)&c_D[l*8 + 4];
                Ya[l] = dot8(a0, a1, d0, d1);
                Yb[l] = dot8(b0, b1, d0, d1);
            }
        } else {
            const float4 a0 = *(const float4*)(pW + ra*SAW);
            const float4 b0 = *(const float4*)(pW + rb*SAW);
            #pragma unroll
            for (int l = 0; l < 8; l++) {
                const float4 d0 = *(const float4*)&c_D[l*8];
                const float4 d1 = *(const float4*)&c_D[l*8 + 4];
                float e0 = d0.x + d0.y, e1 = d0.z + d0.w;
                float e2 = d1.x + d1.y, e3 = d1.z + d1.w;
                Ya[l] = fmaf(a0.w, e3, fmaf(a0.z, e2, fmaf(a0.y, e1, a0.x * e0)));
                Yb[l] = fmaf(b0.w, e3, fmaf(b0.z, e2, fmaf(b0.y, e1, b0.x * e0)));
            }
        }
        {
            const float4 q0  = *(const float4*)&s_qt[c][ra][0];
            const float4 q1  = *(const float4*)&s_qt[c][ra][4];
            const float4 rq0 = *(const float4*)&s_rqt[c][ra][0];
            const float4 rq1 = *(const float4*)&s_rqt[c][ra][4];
            Ya[0] = rintf(rintf(Ya[0]*rq0.x)*q0.x);  Ya[1] = rintf(rintf(Ya[1]*rq0.y)*q0.y);
            Ya[2] = rintf(rintf(Ya[2]*rq0.z)*q0.z);  Ya[3] = rintf(rintf(Ya[3]*rq0.w)*q0.w);
            Ya[4] = rintf(rintf(Ya[4]*rq1.x)*q1.x);  Ya[5] = rintf(rintf(Ya[5]*rq1.y)*q1.y);
            Ya[6] = rintf(rintf(Ya[6]*rq1.z)*q1.z);  Ya[7] = rintf(rintf(Ya[7]*rq1.w)*q1.w);
        }
        {
            const float4 q0  = *(const float4*)&s_qt[c][rb][0];
            const float4 q1  = *(const float4*)&s_qt[c][rb][4];
            const float4 rq0 = *(const float4*)&s_rqt[c][rb][0];
            const float4 rq1 = *(const float4*)&s_rqt[c][rb][4];
            Yb[0] = rintf(rintf(Yb[0]*rq0.x)*q0.x);  Yb[1] = rintf(rintf(Yb[1]*rq0.y)*q0.y);
            Yb[2] = rintf(rintf(Yb[2]*rq0.z)*q0.z);  Yb[3] = rintf(rintf(Yb[3]*rq0.w)*q0.w);
            Yb[4] = rintf(rintf(Yb[4]*rq1.x)*q1.x);  Yb[5] = rintf(rintf(Yb[5]*rq1.y)*q1.y);
            Yb[6] = rintf(rintf(Yb[6]*rq1.z)*q1.z);  Yb[7] = rintf(rintf(Yb[7]*rq1.w)*q1.w);
        }
        __syncwarp();   // all T1^T reads done -> safe to overwrite

        // ==== stage C: G = Y2'^T * D; write transposed (W = D^T*Y2') ====
        {
            float Ga[8], Gb[8];
            #pragma unroll
            for (int l = 0; l < 8; l++) { Ga[l] = 0.0f; Gb[l] = 0.0f; }
            #pragma unroll
            for (int k = 0; k < 8; k++) {
                const float4 d0 = *(const float4*)&c_D[k*8];
                const float4 d1 = *(const float4*)&c_D[k*8 + 4];
                const float t0 = Ya[k], t1 = Yb[k];
                Ga[0] = fmaf(t0, d0.x, Ga[0]);  Gb[0] = fmaf(t1, d0.x, Gb[0]);
                Ga[1] = fmaf(t0, d0.y, Ga[1]);  Gb[1] = fmaf(t1, d0.y, Gb[1]);
                Ga[2] = fmaf(t0, d0.z, Ga[2]);  Gb[2] = fmaf(t1, d0.z, Gb[2]);
                Ga[3] = fmaf(t0, d0.w, Ga[3]);  Gb[3] = fmaf(t1, d0.w, Gb[3]);
                Ga[4] = fmaf(t0, d1.x, Ga[4]);  Gb[4] = fmaf(t1, d1.x, Gb[4]);
                Ga[5] = fmaf(t0, d1.y, Ga[5]);  Gb[5] = fmaf(t1, d1.y, Gb[5]);
                Ga[6] = fmaf(t0, d1.z, Ga[6]);  Gb[6] = fmaf(t1, d1.z, Gb[6]);
                Ga[7] = fmaf(t0, d1.w, Ga[7]);  Gb[7] = fmaf(t1, d1.w, Gb[7]);
            }
            #pragma unroll
            for (int j = 0; j < 8; j++)
                *(float2*)(pW + j*SAW + ra) = make_float2(Ga[j], Gb[j]);
        }
        __syncwarp();

        // ==== stage D: Z = W*D (row-local), +off, write normal ====
        {
            const float4 wa0 = *(const float4*)(pW + ra*SAW);
            const float4 wa1 = *(const float4*)(pW + ra*SAW + 4);
            const float4 wb0 = *(const float4*)(pW + rb*SAW);
            const float4 wb1 = *(const float4*)(pW + rb*SAW + 4);
            float Za[8], Zb[8];
            const float off = (c == 0) ? 128.0f : 0.0f;
            #pragma unroll
            for (int l = 0; l < 8; l++) {
                const float4 dt0 = make_float4(c_D[l], c_D[8+l], c_D[16+l], c_D[24+l]);
                const float4 dt1 = make_float4(c_D[32+l], c_D[40+l], c_D[48+l], c_D[56+l]);
                Za[l] = dot8(wa0, wa1, dt0, dt1) + off;
                Zb[l] = dot8(wb0, wb1, dt0, dt1) + off;
            }
            // threads touch only their own rows here: no barrier needed
            *(float4*)(pW + ra*SAW)     = make_float4(Za[0], Za[1], Za[2], Za[3]);
            *(float4*)(pW + ra*SAW + 4) = make_float4(Za[4], Za[5], Za[6], Za[7]);
            *(float4*)(pW + rb*SAW)     = make_float4(Zb[0], Zb[1], Zb[2], Zb[3]);
            *(float4*)(pW + rb*SAW + 4) = make_float4(Zb[4], Zb[5], Zb[6], Zb[7]);
        }
    }
    __syncthreads();

    // ---- phase 5: YCbCr -> RGB, clip, round, store ----
    {
        const int py  = tid >> 4;
        const int px4 = (tid & 15) * 4;
        const float4 yv  = *(const float4*)&s_a[0][py][px4];
        const float4 cbv = *(const float4*)&s_a[1][py][px4];
        const float4 crv = *(const float4*)&s_a[2][py][px4];

        #define FIN(v) (rintf(fminf(fmaxf((v), 0.0f), 255.0f)) * (1.0f/255.0f))
        float4 R, G, Bv;
        R.x = FIN(fmaf(1.402f, crv.x, yv.x));  R.y = FIN(fmaf(1.402f, crv.y, yv.y));
        R.z = FIN(fmaf(1.402f, crv.z, yv.z));  R.w = FIN(fmaf(1.402f, crv.w, yv.w));
        G.x = FIN(fmaf(-0.714136286f, crv.x, fmaf(-0.344136286f, cbv.x, yv.x)));
        G.y = FIN(fmaf(-0.714136286f, crv.y, fmaf(-0.344136286f, cbv.y, yv.y)));
        G.z = FIN(fmaf(-0.714136286f, crv.z, fmaf(-0.344136286f, cbv.z, yv.z)));
        G.w = FIN(fmaf(-0.714136286f, crv.w, fmaf(-0.344136286f, cbv.w, yv.w)));
        Bv.x = FIN(fmaf(1.772f, cbv.x, yv.x)); Bv.y = FIN(fmaf(1.772f, cbv.y, yv.y));
        Bv.z = FIN(fmaf(1.772f, cbv.z, yv.z)); Bv.w = FIN(fmaf(1.772f, cbv.w, yv.w));

        const size_t idx = (size_t)(ty0 + py) * WIMG + (tx0 + px4);
        *(float4*)&obase[idx]           = R;
        *(float4*)&obase[plane + idx]   = G;
        *(float4*)&obase[2*plane + idx] = Bv;
    }
}

extern "C" void kernel_launch(void* const* d_in, const int* in_sizes, int n_in,
                              void* d_out, int out_size)
{
    const float* x = nullptr;
    const float* q = nullptr;
    const float* d = nullptr;
    int nimg = 0;
    for (int i = 0; i < n_in; i++) {
        if (in_sizes[i] == 192)      q = (const float*)d_in[i];
        else if (in_sizes[i] == 64)  d = (const float*)d_in[i];
        else { x = (const float*)d_in[i]; nimg = in_sizes[i] / (3 * HIMG * WIMG); }
    }
    cudaMemcpyToSymbolAsync(c_D, d, 64 * sizeof(float), 0,
                            cudaMemcpyDeviceToDevice, 0);
    dim3 grid(WIMG / TW, HIMG / TH, nimg);
    jpeg_kernel<<<grid, NT>>>(x, q, d, (float*)d_out);
}